// round 15
// baseline (speedup 1.0000x reference)
#include <cuda_runtime.h>
#include <cstdint>

#define NB 16
#define TN 8
#define CC 1024
#define NH 16
#define HD 64
#define TP 4096
#define TF 4104
#define CH 64
#define NCHUNK 64
#define KSPLIT 4
#define KPER (CC / KSPLIT)            // 256
#define M0 8.0f
#define UNITS_PER_BH 8
#define NUNITS (256 * UNITS_PER_BH)   // 2048
#define UPSTRIDE 528

#define OUT_K_OFF  131072
#define KV_ELEMS   67239936           // 256*4104*64
#define OUT_V_OFF  (OUT_K_OFF + KV_ELEMS)

// attn dynamic smem (floats):
// ks 8192 | vs 8192 | qs 512 | pb 1056 (dup pairs, stride 66 u64/q) | yt 512 | ls 8 | su 4
#define SM_QS  16384
#define SM_PB  16896
#define SM_YT  17952
#define SM_LS  18464
#define SM_SU  18472
#define ATTN_FLOATS 18476
#define ATTN_SMEM (ATTN_FLOATS * 4)   // 73904 B -> 3 CTAs/SM

typedef unsigned long long u64;

// scratch (allocation-free rule: __device__ globals)
__device__ __align__(16) float g_q[256 * TN * HD];          // scaled q, [b][h][t][d]
__device__ __align__(16) float g_y[128 * CC];               // attention out (B,T,C)
__device__ __align__(16) float g_part[KSPLIT * 128 * 3072]; // split-k partials
__device__ __align__(16) float g_upart[NUNITS * UPSTRIDE];  // per-unit (y, l)
__device__ int g_ctr;                                        // persistent work counter
__device__ int g_bhcnt[256];                                 // per-(b,h) finished parts

// ---------------------------------------------------------------------------
// packed fp32x2 helpers (sm_103a FFMA2 — exact fp32, 2x fma-pipe throughput)
// ---------------------------------------------------------------------------
__device__ __forceinline__ u64 ffma2(u64 a, u64 b, u64 c) {
    u64 d;
    asm("fma.rn.f32x2 %0, %1, %2, %3;" : "=l"(d) : "l"(a), "l"(b), "l"(c));
    return d;
}
__device__ __forceinline__ u64 dup2(float x) {
    u64 r; asm("mov.b64 %0, {%1, %2};" : "=l"(r) : "f"(x), "f"(x)); return r;
}
__device__ __forceinline__ float2 up2(u64 v) {
    float2 f; asm("mov.b64 {%0, %1}, %2;" : "=f"(f.x), "=f"(f.y) : "l"(v)); return f;
}

// ---------------------------------------------------------------------------
// Split-K GEMM partial (FFMA2 inner loop). 256 threads, 4x4 register tile.
// MODE 0: X = x input, NCOLS=3072 (QKV).  MODE 1: X = g_y, NCOLS=1024 (proj).
// ---------------------------------------------------------------------------
template <int MODE>
__global__ __launch_bounds__(256) void gemm_partial(
    const float* __restrict__ Xp, const float* __restrict__ W)
{
    const int NCOLS = MODE ? 1024 : 3072;
    const float* X = MODE ? (const float*)g_y : Xp;

    __shared__ float xs[32][68];   // [k][row]
    __shared__ float ws[32][68];   // [k][col]

    const int tid = threadIdx.x;
    const int tx  = tid & 15, ty = tid >> 4;
    const int n0  = blockIdx.x * 64;
    const int r0  = blockIdx.y * 64;
    const int k0  = blockIdx.z * KPER;

    u64 a01[4], a23[4];
#pragma unroll
    for (int i = 0; i < 4; i++) { a01[i] = 0ull; a23[i] = 0ull; }

    const int lrow = tid >> 3, lkq = tid & 7;

    for (int kt = 0; kt < KPER; kt += 32) {
        const int kb = k0 + kt;
#pragma unroll
        for (int h = 0; h < 2; h++) {
            int r = lrow + h * 32;
            float4 xv = *(const float4*)&X[(size_t)(r0 + r) * CC + kb + lkq * 4];
            xs[lkq * 4 + 0][r] = xv.x; xs[lkq * 4 + 1][r] = xv.y;
            xs[lkq * 4 + 2][r] = xv.z; xs[lkq * 4 + 3][r] = xv.w;
            float4 wv = *(const float4*)&W[(size_t)(n0 + r) * CC + kb + lkq * 4];
            ws[lkq * 4 + 0][r] = wv.x; ws[lkq * 4 + 1][r] = wv.y;
            ws[lkq * 4 + 2][r] = wv.z; ws[lkq * 4 + 3][r] = wv.w;
        }
        __syncthreads();
#pragma unroll
        for (int k = 0; k < 32; k++) {
            float4 a = *(const float4*)&xs[k][ty * 4];          // broadcast
            ulonglong2 b2 = *(const ulonglong2*)&ws[k][tx * 4];
            float av[4] = {a.x, a.y, a.z, a.w};
#pragma unroll
            for (int i = 0; i < 4; i++) {
                u64 ad = dup2(av[i]);                           // alu pipe
                a01[i] = ffma2(ad, b2.x, a01[i]);
                a23[i] = ffma2(ad, b2.y, a23[i]);
            }
        }
        __syncthreads();
    }

    float* dst = g_part + (size_t)blockIdx.z * 128 * NCOLS;
#pragma unroll
    for (int i = 0; i < 4; i++) {
        float2 l01 = up2(a01[i]), l23 = up2(a23[i]);
        *(float4*)&dst[(size_t)(r0 + ty * 4 + i) * NCOLS + n0 + tx * 4] =
            make_float4(l01.x, l01.y, l23.x, l23.y);
    }
}

// ---------------------------------------------------------------------------
// Split-K reduce + bias + scatter.
// MODE 0: -> g_q (scaled 0.125), out_k/out_v tails; resets g_ctr / g_bhcnt.
// MODE 1: -> out[row*1024 + n].
// ---------------------------------------------------------------------------
template <int MODE>
__global__ __launch_bounds__(256) void gemm_reduce(
    const float* __restrict__ bias, float* __restrict__ out,
    float* __restrict__ outk, float* __restrict__ outv)
{
    const int NCOLS = MODE ? 1024 : 3072;
    const int gid = blockIdx.x * 256 + threadIdx.x;
    const int row = gid / (NCOLS / 4);
    const int n   = (gid % (NCOLS / 4)) * 4;

    float4 s = make_float4(0.f, 0.f, 0.f, 0.f);
#pragma unroll
    for (int p = 0; p < KSPLIT; p++) {
        float4 v = *(const float4*)&g_part[(size_t)p * 128 * NCOLS + (size_t)row * NCOLS + n];
        s.x += v.x; s.y += v.y; s.z += v.z; s.w += v.w;
    }
    float4 bv = *(const float4*)&bias[n];
    s.x += bv.x; s.y += bv.y; s.z += bv.z; s.w += bv.w;

    if (MODE == 0) {
        int b = row >> 3, t = row & 7, d = n & 63;
        if (n < 1024) {
            int h = n >> 6;
            float4 q = make_float4(s.x * 0.125f, s.y * 0.125f, s.z * 0.125f, s.w * 0.125f);
            *(float4*)&g_q[((b * NH + h) * TN + t) * HD + d] = q;
        } else if (n < 2048) {
            int h = (n - 1024) >> 6;
            *(float4*)&outk[((size_t)(b * NH + h) * TF + TP + t) * HD + d] = s;
        } else {
            int h = (n - 2048) >> 6;
            *(float4*)&outv[((size_t)(b * NH + h) * TF + TP + t) * HD + d] = s;
        }
        if (gid == 0) g_ctr = 0;
        if (gid < 256) g_bhcnt[gid] = 0;
    } else {
        *(float4*)&out[(size_t)row * 1024 + n] = s;
    }
}

// ---------------------------------------------------------------------------
__device__ __forceinline__ void cpa16(void* dst, const void* src) {
    uint32_t d = (uint32_t)__cvta_generic_to_shared(dst);
    asm volatile("cp.async.cg.shared.global [%0], [%1], 16;\n" ::"r"(d), "l"(src));
}

// ---------------------------------------------------------------------------
// Persistent fused KV-cache copy + attention. grid = 3*SMs, 256 thr, 3 CTAs/SM.
// Unit = (b,h) x key-range of 8 chunks (part 7 adds the 8-key causal tail).
// Per chunk only TWO barriers:
//   wait -> A -> [issue next chunk; copy-out; scores + shfl-reduce + fixed-max
//   softmax -> pb] -> B -> [PV] -> (next iteration's A closes all hazards).
// The 8th finisher of each (b,h) combines the 8 fixed slots in fixed order
// (deterministic) -> g_y, eliminating the separate combine launch.
// ---------------------------------------------------------------------------
__global__ __launch_bounds__(256, 3) void attn_kernel(
    const float* __restrict__ pk, const float* __restrict__ pv,
    float* __restrict__ outk, float* __restrict__ outv)
{
    extern __shared__ float sm[];
    float4* ks4 = (float4*)sm;              // 2 bufs * 1024 f4
    float4* vs4 = ks4 + 2048;               // 2 bufs * 1024 f4
    float*  qs  = sm + SM_QS;               // 512
    float*  pb  = sm + SM_PB;               // 1056 (u64 stride 66 per q)
    float*  yt  = sm + SM_YT;               // 512
    float*  ls  = sm + SM_LS;               // 8
    int*    su  = (int*)(sm + SM_SU);       // [0] first unit, [1] next, [2] finish

    const int tid  = threadIdx.x;
    const int w    = tid >> 5, lane = tid & 31;
    const int skey = tid >> 2;              // score mapping: key 0..63
    const int sd   = tid & 3;               // 16-d quarter

    if (tid == 0) su[0] = atomicAdd(&g_ctr, 1);
    __syncthreads();
    int u = su[0];
    if (u >= NUNITS) return;

    int icnt = 0, ccnt = 0;

    int bh = u >> 3, part = u & 7;
    const float* pkb = pk + (size_t)bh * TP * HD;
    const float* pvb = pv + (size_t)bh * TP * HD;
    float* okb = outk + (size_t)bh * TF * HD;
    float* ovb = outv + (size_t)bh * TF * HD;

    auto issue_raw = [&](const float* ksrc, const float* vsrc, int n16, int buf) {
        float4* kb = ks4 + buf * 1024;
        float4* vb = vs4 + buf * 1024;
#pragma unroll
        for (int i = 0; i < 4; i++) {
            int fi = tid + i * 256;
            if (fi < n16) {
                int ky = fi >> 4, f = fi & 15;
                int sidx = ky * 16 + (f ^ (ky & 15));   // XOR swizzle (16B)
                cpa16(kb + sidx, ksrc + fi * 4);
                cpa16(vb + sidx, vsrc + fi * 4);
            }
        }
        asm volatile("cp.async.commit_group;\n");
    };
    auto issue_c = [&](int c, int buf) {
        if (c < NCHUNK)
            issue_raw(pkb + (size_t)c * CH * HD, pvb + (size_t)c * CH * HD, CH * 16, buf);
        else
            issue_raw(okb + (size_t)TP * HD, ovb + (size_t)TP * HD, TN * 16, buf);
    };

    issue_c(part * 8, (icnt++) & 1);

    if (tid < 128) {
        ((float4*)qs)[tid] = ((const float4*)g_q)[bh * 128 + tid];
        ((float4*)yt)[tid] = make_float4(0.f, 0.f, 0.f, 0.f);
    }
    if (tid < 8) ls[tid] = 0.f;

    for (;;) {
        const int c0  = part * 8;
        const int nch = (part == 7) ? 9 : 8;
        if (tid == 0) su[1] = atomicAdd(&g_ctr, 1);   // prefetch next unit id

        float lacc0 = 0.f, lacc1 = 0.f;
        u64 y2[8];
#pragma unroll
        for (int q = 0; q < 8; q++) y2[q] = 0ull;

        int un = NUNITS;

        for (int ci = 0; ci < nch; ci++) {
            const int c = c0 + ci;
            asm volatile("cp.async.wait_group 0;\n");
            __syncthreads();   // A: data visible; prior PV done; su[1]/qs/yt ordered

            if (ci + 1 < nch) {
                issue_c(c + 1, (icnt++) & 1);
            } else {
                un = su[1];
                if (un < NUNITS) {          // next unit's chunk 0 (never a tail)
                    int nbh = un >> 3, npart = un & 7;
                    issue_raw(pk + (size_t)nbh * TP * HD + (size_t)npart * 8 * CH * HD,
                              pv + (size_t)nbh * TP * HD + (size_t)npart * 8 * CH * HD,
                              CH * 16, (icnt++) & 1);
                } else {
                    asm volatile("cp.async.commit_group;\n");   // keep parity harmless
                }
            }

            const int buf = (ccnt++) & 1;
            const float4*     kb  = ks4 + buf * 1024;
            const float4*     vb  = vs4 + buf * 1024;
            const ulonglong2* kb2 = (const ulonglong2*)kb;
            const float*      vbf = (const float*)vb;

            // coalesced copy-out (the "write KV cache" half of the fusion)
            if (c < NCHUNK) {
#pragma unroll
                for (int i = 0; i < 4; i++) {
                    int fi = tid + i * 256;
                    int ky = fi >> 4, f = fi & 15;
                    int sidx = ky * 16 + (f ^ (ky & 15));
                    *(float4*)&okb[(size_t)c * 4096 + fi * 4] = kb[sidx];
                    *(float4*)&ovb[(size_t)c * 4096 + fi * 4] = vb[sidx];
                }
            }

            // ---- scores: thread (skey, sd) covers 16 d's for all 8 q ----
            ulonglong2 kv2[4];
#pragma unroll
            for (int i = 0; i < 4; i++)
                kv2[i] = kb2[skey * 16 + ((sd * 4 + i) ^ (skey & 15))];
            float ps[8];
#pragma unroll
            for (int q = 0; q < 8; q++) {
                u64 s2 = 0ull;
#pragma unroll
                for (int i = 0; i < 4; i++) {
                    ulonglong2 qv2 = ((const ulonglong2*)qs)[q * 16 + sd * 4 + i];
                    s2 = ffma2(kv2[i].x, qv2.x, s2);
                    s2 = ffma2(kv2[i].y, qv2.y, s2);
                }
                float2 ss = up2(s2);
                ps[q] = ss.x + ss.y;
            }
            // reduce the 4 d-quarters (adjacent lanes share skey)
#pragma unroll
            for (int q = 0; q < 8; q++) {
                ps[q] += __shfl_xor_sync(0xffffffffu, ps[q], 1);
                ps[q] += __shfl_xor_sync(0xffffffffu, ps[q], 2);
            }
            if (c == NCHUNK) {      // causal mask on the 8 new keys
#pragma unroll
                for (int q = 0; q < 8; q++)
                    if (!(skey < TN && skey <= q)) ps[q] = -1e30f;
            }
            // fixed-max softmax: this lane finalizes q = 2*sd, 2*sd+1
            {
                int q0 = 2 * sd;
                float p0 = __expf(ps[q0]     - M0);
                float p1 = __expf(ps[q0 + 1] - M0);
                lacc0 += p0; lacc1 += p1;
                ((u64*)pb)[(size_t)q0 * 66 + skey]       = dup2(p0);
                ((u64*)pb)[(size_t)(q0 + 1) * 66 + skey] = dup2(p1);
            }
            __syncthreads();   // B: pb ready

            // ---- PV (FFMA2): warp w -> keys w*8..w*8+7, lane -> d pair ----
            {
                u64 vvp[8];
#pragma unroll
                for (int jj = 0; jj < 8; jj++) {
                    int j  = w * 8 + jj;
                    int fo = (j * 16 + ((lane >> 1) ^ (j & 15))) * 4 + ((2 * lane) & 3);
                    vvp[jj] = *(const u64*)&vbf[fo];
                }
#pragma unroll
                for (int q = 0; q < 8; q++) {
                    ulonglong2 p0 = ((const ulonglong2*)pb)[q * 33 + w * 4 + 0]; // uniform
                    ulonglong2 p1 = ((const ulonglong2*)pb)[q * 33 + w * 4 + 1];
                    ulonglong2 p2 = ((const ulonglong2*)pb)[q * 33 + w * 4 + 2];
                    ulonglong2 p3 = ((const ulonglong2*)pb)[q * 33 + w * 4 + 3];
                    u64 acc = y2[q];
                    acc = ffma2(p0.x, vvp[0], acc); acc = ffma2(p0.y, vvp[1], acc);
                    acc = ffma2(p1.x, vvp[2], acc); acc = ffma2(p1.y, vvp[3], acc);
                    acc = ffma2(p2.x, vvp[4], acc); acc = ffma2(p2.y, vvp[5], acc);
                    acc = ffma2(p3.x, vvp[6], acc); acc = ffma2(p3.y, vvp[7], acc);
                    y2[q] = acc;
                }
            }
            // no end barrier: next iteration's A closes pb / buffer hazards
        }

        // ---- unit epilogue ----
#pragma unroll
        for (int q = 0; q < 8; q++) {
            float2 yq = up2(y2[q]);
            atomicAdd(&yt[q * 64 + 2 * lane],     yq.x);
            atomicAdd(&yt[q * 64 + 2 * lane + 1], yq.y);
        }
        // l: sum over the 8 skeys of this warp (lanes sharing sd), then smem
        lacc0 += __shfl_xor_sync(0xffffffffu, lacc0, 4);
        lacc0 += __shfl_xor_sync(0xffffffffu, lacc0, 8);
        lacc0 += __shfl_xor_sync(0xffffffffu, lacc0, 16);
        lacc1 += __shfl_xor_sync(0xffffffffu, lacc1, 4);
        lacc1 += __shfl_xor_sync(0xffffffffu, lacc1, 8);
        lacc1 += __shfl_xor_sync(0xffffffffu, lacc1, 16);
        if (lane < 4) {
            atomicAdd(&ls[2 * lane],     lacc0);
            atomicAdd(&ls[2 * lane + 1], lacc1);
        }
        __syncthreads();

        float* up = g_upart + (size_t)u * UPSTRIDE;
        if (tid < 128) ((float4*)up)[tid] = ((const float4*)yt)[tid];
        if (tid < 8)   up[512 + tid] = ls[tid];
        __threadfence();
        __syncthreads();
        if (tid == 0) su[2] = atomicAdd(&g_bhcnt[bh], 1);
        __syncthreads();
        if (su[2] == 7) {          // 8th finisher combines bh (fixed order)
            __threadfence();
            if (tid < 128) {
                int q = tid >> 4, d4 = tid & 15;
                float4 ys = make_float4(0.f, 0.f, 0.f, 0.f);
                float  lsum = 0.f;
#pragma unroll
                for (int p = 0; p < UNITS_PER_BH; p++) {
                    const float* upp = g_upart + (size_t)(bh * UNITS_PER_BH + p) * UPSTRIDE;
                    float4 v = ((const float4*)upp)[tid];
                    ys.x += v.x; ys.y += v.y; ys.z += v.z; ys.w += v.w;
                    lsum += upp[512 + q];
                }
                float inv = 1.f / lsum;
                ys.x *= inv; ys.y *= inv; ys.z *= inv; ys.w *= inv;
                int b = bh >> 4, h = bh & 15;
                *(float4*)&g_y[(size_t)(b * TN + q) * CC + h * HD + d4 * 4] = ys;
            }
        }

        u = un;
        if (u >= NUNITS) break;
        bh = u >> 3; part = u & 7;
        pkb = pk + (size_t)bh * TP * HD;
        pvb = pv + (size_t)bh * TP * HD;
        okb = outk + (size_t)bh * TF * HD;
        ovb = outv + (size_t)bh * TF * HD;
        __syncthreads();           // slot writes / combine reads done before re-init
        if (tid < 128) {
            ((float4*)qs)[tid] = ((const float4*)g_q)[bh * 128 + tid];
            ((float4*)yt)[tid] = make_float4(0.f, 0.f, 0.f, 0.f);
        }
        if (tid < 8) ls[tid] = 0.f;
        // next unit's chunk 0 already in flight (issued post-A of last chunk)
    }
}

// ---------------------------------------------------------------------------
extern "C" void kernel_launch(void* const* d_in, const int* in_sizes, int n_in,
                              void* d_out, int out_size)
{
    const float* x      = (const float*)d_in[0];
    const float* past_k = (const float*)d_in[1];
    const float* past_v = (const float*)d_in[2];
    const float* W_attn = (const float*)d_in[3];
    const float* b_attn = (const float*)d_in[4];
    const float* W_proj = (const float*)d_in[5];
    const float* b_proj = (const float*)d_in[6];

    float* out  = (float*)d_out;
    float* outk = out + OUT_K_OFF;
    float* outv = out + OUT_V_OFF;

    int dev = 0, nsm = 148;
    cudaGetDevice(&dev);
    cudaDeviceGetAttribute(&nsm, cudaDevAttrMultiProcessorCount, dev);

    // host-side attribute set — not a stream op, capture-safe
    cudaFuncSetAttribute(attn_kernel, cudaFuncAttributeMaxDynamicSharedMemorySize,
                         ATTN_SMEM);

    // 1) QKV projection (split-K=4): partials -> reduce -> g_q + out k/v tails
    gemm_partial<0><<<dim3(48, 2, KSPLIT), 256>>>(x, W_attn);
    gemm_reduce<0><<<384, 256>>>(b_attn, nullptr, outk, outv);

    // 2) persistent fused KV-copy + attention (+ in-kernel combine -> g_y)
    attn_kernel<<<3 * nsm, 256, ATTN_SMEM>>>(past_k, past_v, outk, outv);

    // 3) output projection (split-K=4)
    gemm_partial<1><<<dim3(16, 2, KSPLIT), 256>>>(nullptr, W_proj);
    gemm_reduce<1><<<128, 256>>>(b_proj, out, nullptr, nullptr);
}

// round 16
// speedup vs baseline: 1.3577x; 1.3577x over previous
#include <cuda_runtime.h>
#include <cstdint>

#define NB 16
#define TN 8
#define CC 1024
#define NH 16
#define HD 64
#define TP 4096
#define TF 4104
#define CH 64
#define NCHUNK 64
#define KSPLIT 8
#define KPER (CC / KSPLIT)            // 128
#define M0 8.0f
#define UNITS_PER_BH 8
#define NUNITS (256 * UNITS_PER_BH)   // 2048
#define UPSTRIDE 528

#define OUT_K_OFF  131072
#define KV_ELEMS   67239936           // 256*4104*64
#define OUT_V_OFF  (OUT_K_OFF + KV_ELEMS)

// attn dynamic smem (floats): ks 8192 | vs 8192 | qs 512 | sp 2048 | pb 1024(dup) | yt 512 | su 4
#define ATTN_SMEM ((8192 + 8192 + 512 + 2048 + 1024 + 512 + 4) * 4)

typedef unsigned long long u64;

// scratch (allocation-free rule: __device__ globals)
__device__ __align__(16) float g_q[256 * TN * HD];          // scaled q, [b][h][t][d]
__device__ __align__(16) float g_y[128 * CC];               // attention out (B,T,C)
__device__ __align__(16) float g_part[KSPLIT * 128 * 3072]; // split-k partials
__device__ __align__(16) float g_upart[NUNITS * UPSTRIDE];  // per-unit (y, l)
__device__ int g_ctr;                                        // persistent work counter

// ---------------------------------------------------------------------------
// packed fp32x2 helpers (sm_103a FFMA2 — exact fp32, 2x fma-pipe throughput)
// ---------------------------------------------------------------------------
__device__ __forceinline__ u64 ffma2(u64 a, u64 b, u64 c) {
    u64 d;
    asm("fma.rn.f32x2 %0, %1, %2, %3;" : "=l"(d) : "l"(a), "l"(b), "l"(c));
    return d;
}
__device__ __forceinline__ u64 dup2(float x) {
    u64 r; asm("mov.b64 %0, {%1, %2};" : "=l"(r) : "f"(x), "f"(x)); return r;
}
__device__ __forceinline__ float2 up2(u64 v) {
    float2 f; asm("mov.b64 {%0, %1}, %2;" : "=f"(f.x), "=f"(f.y) : "l"(v)); return f;
}

// ---------------------------------------------------------------------------
// Split-K GEMM partial (FFMA2). 256 threads. Row tile RM (64 or 32), col tile
// 64, thread tile (RM/16) x 4.  RM=32 doubles the grid for latency hiding on
// the small proj GEMM (R15: 128 blocks was grid-starved at 17.5us).
// MODE 0: X = x input, NCOLS=3072 (QKV).  MODE 1: X = g_y, NCOLS=1024 (proj).
// ---------------------------------------------------------------------------
template <int MODE, int RM>
__global__ __launch_bounds__(256) void gemm_partial(
    const float* __restrict__ Xp, const float* __restrict__ W)
{
    const int NCOLS = MODE ? 1024 : 3072;
    const int RPT   = RM / 16;             // rows per thread (4 or 2)
    const float* X = MODE ? (const float*)g_y : Xp;

    __shared__ float xs[32][RM + 4];       // [k][row]
    __shared__ float ws[32][68];           // [k][col]

    const int tid = threadIdx.x;
    const int tx  = tid & 15, ty = tid >> 4;
    const int n0  = blockIdx.x * 64;
    const int r0  = blockIdx.y * RM;
    const int k0  = blockIdx.z * KPER;

    u64 a01[RPT], a23[RPT];
#pragma unroll
    for (int i = 0; i < RPT; i++) { a01[i] = 0ull; a23[i] = 0ull; }

    const int lrow = tid >> 3, lkq = tid & 7;

    for (int kt = 0; kt < KPER; kt += 32) {
        const int kb = k0 + kt;
#pragma unroll
        for (int h = 0; h < RM / 32; h++) {
            int r = lrow + h * 32;
            float4 xv = *(const float4*)&X[(size_t)(r0 + r) * CC + kb + lkq * 4];
            xs[lkq * 4 + 0][r] = xv.x; xs[lkq * 4 + 1][r] = xv.y;
            xs[lkq * 4 + 2][r] = xv.z; xs[lkq * 4 + 3][r] = xv.w;
        }
        {
            int r = lrow;
            float4 wv = *(const float4*)&W[(size_t)(n0 + r) * CC + kb + lkq * 4];
            ws[lkq * 4 + 0][r] = wv.x; ws[lkq * 4 + 1][r] = wv.y;
            ws[lkq * 4 + 2][r] = wv.z; ws[lkq * 4 + 3][r] = wv.w;
            r = lrow + 32;
            wv = *(const float4*)&W[(size_t)(n0 + r) * CC + kb + lkq * 4];
            ws[lkq * 4 + 0][r] = wv.x; ws[lkq * 4 + 1][r] = wv.y;
            ws[lkq * 4 + 2][r] = wv.z; ws[lkq * 4 + 3][r] = wv.w;
        }
        __syncthreads();
#pragma unroll
        for (int k = 0; k < 32; k++) {
            ulonglong2 b2 = *(const ulonglong2*)&ws[k][tx * 4];
            float av[RPT];
            if (RPT == 4) {
                float4 a = *(const float4*)&xs[k][ty * 4];
                av[0] = a.x; av[1] = a.y; av[2] = a.z; av[3] = a.w;
            } else {
                float2 a = *(const float2*)&xs[k][ty * 2];
                av[0] = a.x; av[1] = a.y;
            }
#pragma unroll
            for (int i = 0; i < RPT; i++) {
                u64 ad = dup2(av[i]);                           // alu pipe
                a01[i] = ffma2(ad, b2.x, a01[i]);
                a23[i] = ffma2(ad, b2.y, a23[i]);
            }
        }
        __syncthreads();
    }

    float* dst = g_part + (size_t)blockIdx.z * 128 * NCOLS;
#pragma unroll
    for (int i = 0; i < RPT; i++) {
        float2 l01 = up2(a01[i]), l23 = up2(a23[i]);
        *(float4*)&dst[(size_t)(r0 + ty * RPT + i) * NCOLS + n0 + tx * 4] =
            make_float4(l01.x, l01.y, l23.x, l23.y);
    }
}

// ---------------------------------------------------------------------------
// Split-K reduce + bias + scatter.
// MODE 0: -> g_q (scaled 0.125), out_k/out_v tails; also resets g_ctr.
// MODE 1: -> out[row*1024 + n].
// ---------------------------------------------------------------------------
template <int MODE>
__global__ __launch_bounds__(256) void gemm_reduce(
    const float* __restrict__ bias, float* __restrict__ out,
    float* __restrict__ outk, float* __restrict__ outv)
{
    const int NCOLS = MODE ? 1024 : 3072;
    const int gid = blockIdx.x * 256 + threadIdx.x;
    const int row = gid / (NCOLS / 4);
    const int n   = (gid % (NCOLS / 4)) * 4;

    float4 s = make_float4(0.f, 0.f, 0.f, 0.f);
#pragma unroll
    for (int p = 0; p < KSPLIT; p++) {
        float4 v = *(const float4*)&g_part[(size_t)p * 128 * NCOLS + (size_t)row * NCOLS + n];
        s.x += v.x; s.y += v.y; s.z += v.z; s.w += v.w;
    }
    float4 bv = *(const float4*)&bias[n];
    s.x += bv.x; s.y += bv.y; s.z += bv.z; s.w += bv.w;

    if (MODE == 0) {
        int b = row >> 3, t = row & 7, d = n & 63;
        if (n < 1024) {
            int h = n >> 6;
            float4 q = make_float4(s.x * 0.125f, s.y * 0.125f, s.z * 0.125f, s.w * 0.125f);
            *(float4*)&g_q[((b * NH + h) * TN + t) * HD + d] = q;
        } else if (n < 2048) {
            int h = (n - 1024) >> 6;
            *(float4*)&outk[((size_t)(b * NH + h) * TF + TP + t) * HD + d] = s;
        } else {
            int h = (n - 2048) >> 6;
            *(float4*)&outv[((size_t)(b * NH + h) * TF + TP + t) * HD + d] = s;
        }
        if (gid == 0) g_ctr = 0;    // reset persistent work counter before attn
    } else {
        *(float4*)&out[(size_t)row * 1024 + n] = s;
    }
}

// ---------------------------------------------------------------------------
__device__ __forceinline__ void cpa16(void* dst, const void* src) {
    uint32_t d = (uint32_t)__cvta_generic_to_shared(dst);
    asm volatile("cp.async.cg.shared.global [%0], [%1], 16;\n" ::"r"(d), "l"(src));
}

// ---------------------------------------------------------------------------
// Persistent fused KV-cache copy + attention (R11 structure — validated at
// 227.7us; R15's 3-CTA/2-barrier variant regressed and is reverted).
// grid = 2*SMs, 256 threads, 2 CTAs/SM. Cross-unit cp.async pipelining.
// Fixed-max softmax (M0) keeps partials associative -> deterministic combine.
// ---------------------------------------------------------------------------
__global__ __launch_bounds__(256, 2) void attn_kernel(
    const float* __restrict__ pk, const float* __restrict__ pv,
    float* __restrict__ outk, float* __restrict__ outv)
{
    extern __shared__ float sm[];
    float4* ks4 = (float4*)sm;              // 2 bufs * 1024 f4
    float4* vs4 = ks4 + 2048;               // 2 bufs * 1024 f4
    float*  qs  = (float*)(vs4 + 2048);     // 512
    float*  sp  = qs + 512;                 // 2048 score partials
    float*  pb  = sp + 2048;                // 1024 duplicated probabilities (p,p)
    float*  yt  = pb + 1024;                // 512 y reduction
    int*    su  = (int*)(yt + 512);         // [0]=current unit, [1]=next unit

    const int tid  = threadIdx.x;
    const int w    = tid >> 5, lane = tid & 31;
    const int key  = (w & 1) * 32 + lane;   // score mapping
    const int dseg = w >> 1;

    if (tid == 0) su[0] = atomicAdd(&g_ctr, 1);
    __syncthreads();
    int u = su[0];
    if (u >= NUNITS) return;

    int icnt = 0, ccnt = 0;     // issued / consumed chunk counters (buffer parity)

    int bh = u >> 3, part = u & 7;
    const float* pkb = pk + (size_t)bh * TP * HD;
    const float* pvb = pv + (size_t)bh * TP * HD;
    float* okb = outk + (size_t)bh * TF * HD;
    float* ovb = outv + (size_t)bh * TF * HD;

    auto issue_raw = [&](const float* ksrc, const float* vsrc, int n16, int buf) {
        float4* kb = ks4 + buf * 1024;
        float4* vb = vs4 + buf * 1024;
#pragma unroll
        for (int i = 0; i < 4; i++) {
            int fi = tid + i * 256;
            if (fi < n16) {
                int ky = fi >> 4, f = fi & 15;
                int sidx = ky * 16 + (f ^ (ky & 15));   // XOR swizzle (16B)
                cpa16(kb + sidx, ksrc + fi * 4);
                cpa16(vb + sidx, vsrc + fi * 4);
            }
        }
        asm volatile("cp.async.commit_group;\n");
    };
    auto issue_c = [&](const float* pk_, const float* pv_, float* ok_, float* ov_,
                       int c, int buf) {
        if (c < NCHUNK)
            issue_raw(pk_ + (size_t)c * CH * HD, pv_ + (size_t)c * CH * HD, CH * 16, buf);
        else
            issue_raw(ok_ + (size_t)TP * HD, ov_ + (size_t)TP * HD, TN * 16, buf);
    };

    issue_c(pkb, pvb, okb, ovb, part * 8, (icnt++) & 1);

    if (tid < 128) {
        ((float4*)qs)[tid] = ((const float4*)g_q)[bh * 128 + tid];
        ((float4*)yt)[tid] = make_float4(0.f, 0.f, 0.f, 0.f);
    }

    for (;;) {
        const int c0  = part * 8;
        const int nch = (part == 7) ? 9 : 8;
        if (tid == 0) su[1] = atomicAdd(&g_ctr, 1);   // prefetch next unit id

        float l = 0.f;
        u64 y2[8];
#pragma unroll
        for (int q = 0; q < 8; q++) y2[q] = 0ull;

        int un = NUNITS;

        for (int ci = 0; ci < nch; ci++) {
            const int c = c0 + ci;
            if (ci + 1 < nch) {
                issue_c(pkb, pvb, okb, ovb, c + 1, (icnt++) & 1);
                asm volatile("cp.async.wait_group 1;\n");
            } else {
                un = su[1];   // ordered by the barriers of earlier iterations
                if (un < NUNITS) {
                    int nbh = un >> 3, npart = un & 7;
                    issue_c(pk + (size_t)nbh * TP * HD, pv + (size_t)nbh * TP * HD,
                            outk + (size_t)nbh * TF * HD, outv + (size_t)nbh * TF * HD,
                            npart * 8, (icnt++) & 1);
                    asm volatile("cp.async.wait_group 1;\n");
                } else {
                    asm volatile("cp.async.wait_group 0;\n");
                }
            }
            __syncthreads();   // A: chunk data visible to all threads

            const int buf = (ccnt++) & 1;
            const float4*     kb  = ks4 + buf * 1024;
            const float4*     vb  = vs4 + buf * 1024;
            const ulonglong2* kb2 = (const ulonglong2*)kb;
            const float*      vbf = (const float*)vb;

            // coalesced copy-out (the "write KV cache" half of the fusion)
            if (c < NCHUNK) {
#pragma unroll
                for (int i = 0; i < 4; i++) {
                    int fi = tid + i * 256;
                    int ky = fi >> 4, f = fi & 15;
                    int sidx = ky * 16 + (f ^ (ky & 15));
                    *(float4*)&okb[(size_t)c * 4096 + fi * 4] = kb[sidx];
                    *(float4*)&ovb[(size_t)c * 4096 + fi * 4] = vb[sidx];
                }
            }

            // ---- scores (FFMA2, operands pair-packed for free) ----
            ulonglong2 kv2[4];
#pragma unroll
            for (int i = 0; i < 4; i++)
                kv2[i] = kb2[key * 16 + ((dseg * 4 + i) ^ (key & 15))];
            float ps[8];
#pragma unroll
            for (int q = 0; q < 8; q++) {
                u64 s2 = 0ull;
#pragma unroll
                for (int i = 0; i < 4; i++) {
                    ulonglong2 qv2 = ((const ulonglong2*)qs)[q * 16 + dseg * 4 + i];
                    s2 = ffma2(kv2[i].x, qv2.x, s2);
                    s2 = ffma2(kv2[i].y, qv2.y, s2);
                }
                float2 ss = up2(s2);
                ps[q] = ss.x + ss.y;
            }
#pragma unroll
            for (int q = 0; q < 8; q++)
                sp[dseg * 512 + q * 64 + key] = ps[q];
            __syncthreads();   // B

            // ---- fixed-max softmax: warp w -> query w; write (p,p) pairs ----
            {
                float s1 = sp[w * 64 + lane]        + sp[512 + w * 64 + lane]
                         + sp[1024 + w * 64 + lane] + sp[1536 + w * 64 + lane];
                float s2v = sp[w * 64 + lane + 32]        + sp[512 + w * 64 + lane + 32]
                          + sp[1024 + w * 64 + lane + 32] + sp[1536 + w * 64 + lane + 32];
                if (c == NCHUNK) {      // causal mask on the 8 new keys
                    if (!(lane < TN && lane <= w)) s1 = -1e30f;
                    s2v = -1e30f;
                }
                float p1 = __expf(s1 - M0);
                float p2 = __expf(s2v - M0);
                l += p1 + p2;
                *(u64*)&pb[(w * 64 + lane) * 2]      = dup2(p1);
                *(u64*)&pb[(w * 64 + lane + 32) * 2] = dup2(p2);
            }
            __syncthreads();   // C

            // ---- PV (FFMA2): warp w -> keys w*8..w*8+7, lane -> d pair ----
            {
                u64 vvp[8];
#pragma unroll
                for (int jj = 0; jj < 8; jj++) {
                    int j  = w * 8 + jj;
                    int fo = (j * 16 + ((lane >> 1) ^ (j & 15))) * 4 + ((2 * lane) & 3);
                    vvp[jj] = *(const u64*)&vbf[fo];
                }
#pragma unroll
                for (int q = 0; q < 8; q++) {
                    ulonglong2 p0 = ((const ulonglong2*)pb)[q * 32 + w * 4 + 0]; // uniform
                    ulonglong2 p1 = ((const ulonglong2*)pb)[q * 32 + w * 4 + 1];
                    ulonglong2 p2 = ((const ulonglong2*)pb)[q * 32 + w * 4 + 2];
                    ulonglong2 p3 = ((const ulonglong2*)pb)[q * 32 + w * 4 + 3];
                    u64 acc = y2[q];
                    acc = ffma2(p0.x, vvp[0], acc); acc = ffma2(p0.y, vvp[1], acc);
                    acc = ffma2(p1.x, vvp[2], acc); acc = ffma2(p1.y, vvp[3], acc);
                    acc = ffma2(p2.x, vvp[4], acc); acc = ffma2(p2.y, vvp[5], acc);
                    acc = ffma2(p3.x, vvp[6], acc); acc = ffma2(p3.y, vvp[7], acc);
                    y2[q] = acc;
                }
            }
            __syncthreads();   // D: protects K/V buffer + sp/pb reuse
        }

        // ---- unit epilogue: reduce y across key-group warps, write slot ----
#pragma unroll
        for (int q = 0; q < 8; q++) {
            float2 yq = up2(y2[q]);
            atomicAdd(&yt[q * 64 + 2 * lane],     yq.x);
            atomicAdd(&yt[q * 64 + 2 * lane + 1], yq.y);
        }
#pragma unroll
        for (int o = 16; o > 0; o >>= 1) l += __shfl_xor_sync(0xffffffffu, l, o);
        __syncthreads();
        float* up = g_upart + (size_t)u * UPSTRIDE;
        if (tid < 128) ((float4*)up)[tid] = ((const float4*)yt)[tid];
        if (lane == 0) up[512 + w] = l;

        u = un;
        if (u >= NUNITS) break;
        bh = u >> 3; part = u & 7;
        pkb = pk + (size_t)bh * TP * HD;
        pvb = pv + (size_t)bh * TP * HD;
        okb = outk + (size_t)bh * TF * HD;
        ovb = outv + (size_t)bh * TF * HD;
        __syncthreads();       // upart reads of yt complete before re-zero
        if (tid < 128) {
            ((float4*)qs)[tid] = ((const float4*)g_q)[bh * 128 + tid];
            ((float4*)yt)[tid] = make_float4(0.f, 0.f, 0.f, 0.f);
        }
        // next unit's chunk 0 is already in flight (issued at last chunk above)
    }
}

// ---------------------------------------------------------------------------
// Combine the 8 fixed parts per (b,h): y = sum y_p / sum l_p -> g_y.
// 256 threads: half 0 sums parts 0..3, half 1 sums parts 4..7 (halves the
// dependent-load chain vs R11's 8-deep). Fixed order => deterministic.
// ---------------------------------------------------------------------------
__global__ __launch_bounds__(256) void combine_kernel()
{
    __shared__ float4 red[128];
    __shared__ float  lred[8];

    const int bh   = blockIdx.x;
    const int tid  = threadIdx.x;
    const int half = tid >> 7, t = tid & 127;
    const int q    = t >> 4, d4 = t & 15;

    float4 ys = make_float4(0.f, 0.f, 0.f, 0.f);
    float  ls = 0.f;
#pragma unroll
    for (int p = 0; p < 4; p++) {
        const float* up = g_upart + (size_t)(bh * UNITS_PER_BH + half * 4 + p) * UPSTRIDE;
        float4 v = ((const float4*)up)[t];
        ys.x += v.x; ys.y += v.y; ys.z += v.z; ys.w += v.w;
        ls += up[512 + q];
    }
    if (half == 1) {
        red[t] = ys;
        if (d4 == 0) lred[q] = ls;
    }
    __syncthreads();
    if (half == 0) {
        float4 o = red[t];
        ys.x += o.x; ys.y += o.y; ys.z += o.z; ys.w += o.w;
        ls += lred[q];
        float inv = 1.f / ls;
        ys.x *= inv; ys.y *= inv; ys.z *= inv; ys.w *= inv;
        int b = bh >> 4, h = bh & 15;
        *(float4*)&g_y[(size_t)(b * TN + q) * CC + h * HD + d4 * 4] = ys;
    }
}

// ---------------------------------------------------------------------------
extern "C" void kernel_launch(void* const* d_in, const int* in_sizes, int n_in,
                              void* d_out, int out_size)
{
    const float* x      = (const float*)d_in[0];
    const float* past_k = (const float*)d_in[1];
    const float* past_v = (const float*)d_in[2];
    const float* W_attn = (const float*)d_in[3];
    const float* b_attn = (const float*)d_in[4];
    const float* W_proj = (const float*)d_in[5];
    const float* b_proj = (const float*)d_in[6];

    float* out  = (float*)d_out;
    float* outk = out + OUT_K_OFF;
    float* outv = out + OUT_V_OFF;

    int dev = 0, nsm = 148;
    cudaGetDevice(&dev);
    cudaDeviceGetAttribute(&nsm, cudaDevAttrMultiProcessorCount, dev);

    // host-side attribute set — not a stream op, capture-safe
    cudaFuncSetAttribute(attn_kernel, cudaFuncAttributeMaxDynamicSharedMemorySize,
                         ATTN_SMEM);

    // 1) QKV projection (split-K=8): partials -> reduce -> g_q + out k/v tails
    gemm_partial<0, 64><<<dim3(48, 2, KSPLIT), 256>>>(x, W_attn);
    gemm_reduce<0><<<384, 256>>>(b_attn, nullptr, outk, outv);

    // 2) persistent fused KV-copy + attention, then deterministic combine
    attn_kernel<<<2 * nsm, 256, ATTN_SMEM>>>(past_k, past_v, outk, outv);
    combine_kernel<<<256, 256>>>();

    // 3) output projection (split-K=8, RM=32 -> 512 blocks for latency hiding)
    gemm_partial<1, 32><<<dim3(16, 4, KSPLIT), 256>>>(nullptr, W_proj);
    gemm_reduce<1><<<128, 256>>>(b_proj, out, nullptr, nullptr);
}